// round 1
// baseline (speedup 1.0000x reference)
#include <cuda_runtime.h>
#include <cuda_bf16.h>
#include <math.h>

// Problem constants
#define B_   2
#define S_   2048
#define D_   2048
#define H_   32
#define KV_  8
#define HD_  64

// Scratch (static device globals: allocation-free, graph-safe)
__device__ float g_q[B_ * S_ * H_ * HD_];     // 32 MB
__device__ float g_k[B_ * S_ * KV_ * HD_];    // 8 MB
__device__ float g_v[B_ * S_ * KV_ * HD_];    // 8 MB
__device__ float g_attn[B_ * S_ * H_ * HD_];  // 32 MB

// ---------------------------------------------------------------------------
// SGEMM: C[M,N] = A[M,K] * B[N,K]^T   (all row-major; M%128==0, N%128==0, K%16==0)
// 128x128 block tile, BK=16, 256 threads, 8x8 per-thread microtile.
// ---------------------------------------------------------------------------
__global__ __launch_bounds__(256) void gemm_nt(const float* __restrict__ A,
                                               const float* __restrict__ Bm,
                                               float* __restrict__ C,
                                               int M, int N, int K) {
    __shared__ float As[16][128];
    __shared__ float Bs[16][128];

    const int tid = threadIdx.x;
    const int tx  = tid & 15;   // column group
    const int ty  = tid >> 4;   // row group

    const float* Ab = A  + (size_t)blockIdx.y * 128 * K;
    const float* Bb = Bm + (size_t)blockIdx.x * 128 * K;

    const int lr = tid >> 2;          // 0..63
    const int lc = (tid & 3) << 2;    // 0,4,8,12

    float acc[8][8];
#pragma unroll
    for (int i = 0; i < 8; i++)
#pragma unroll
        for (int j = 0; j < 8; j++) acc[i][j] = 0.f;

    for (int k0 = 0; k0 < K; k0 += 16) {
#pragma unroll
        for (int l = 0; l < 2; l++) {
            int row = lr + l * 64;
            float4 va = *reinterpret_cast<const float4*>(Ab + (size_t)row * K + k0 + lc);
            As[lc + 0][row] = va.x; As[lc + 1][row] = va.y;
            As[lc + 2][row] = va.z; As[lc + 3][row] = va.w;
            float4 vb = *reinterpret_cast<const float4*>(Bb + (size_t)row * K + k0 + lc);
            Bs[lc + 0][row] = vb.x; Bs[lc + 1][row] = vb.y;
            Bs[lc + 2][row] = vb.z; Bs[lc + 3][row] = vb.w;
        }
        __syncthreads();

#pragma unroll
        for (int kk = 0; kk < 16; kk++) {
            float4 a0 = *reinterpret_cast<const float4*>(&As[kk][ty * 8]);
            float4 a1 = *reinterpret_cast<const float4*>(&As[kk][ty * 8 + 4]);
            float4 b0 = *reinterpret_cast<const float4*>(&Bs[kk][tx * 8]);
            float4 b1 = *reinterpret_cast<const float4*>(&Bs[kk][tx * 8 + 4]);
            float ra[8] = {a0.x, a0.y, a0.z, a0.w, a1.x, a1.y, a1.z, a1.w};
            float rb[8] = {b0.x, b0.y, b0.z, b0.w, b1.x, b1.y, b1.z, b1.w};
#pragma unroll
            for (int i = 0; i < 8; i++)
#pragma unroll
                for (int j = 0; j < 8; j++)
                    acc[i][j] += ra[i] * rb[j];
        }
        __syncthreads();
    }

    float* Cb = C + (size_t)(blockIdx.y * 128 + ty * 8) * N + blockIdx.x * 128 + tx * 8;
#pragma unroll
    for (int i = 0; i < 8; i++) {
        float4 c0 = make_float4(acc[i][0], acc[i][1], acc[i][2], acc[i][3]);
        float4 c1 = make_float4(acc[i][4], acc[i][5], acc[i][6], acc[i][7]);
        *reinterpret_cast<float4*>(Cb + (size_t)i * N)     = c0;
        *reinterpret_cast<float4*>(Cb + (size_t)i * N + 4) = c1;
    }
}

// ---------------------------------------------------------------------------
// RoPE (in place): t shape (B*S, heads*64). Pair (i, i+32) rotated by
// cos/sin[s, i] (cos/sin are (S, 32) row-major).
// ---------------------------------------------------------------------------
__global__ void rope_kernel(float* __restrict__ t, const float* __restrict__ cs,
                            const float* __restrict__ sn, int heads) {
    int idx = blockIdx.x * blockDim.x + threadIdx.x;
    int total = B_ * S_ * heads * 32;
    if (idx >= total) return;
    int i   = idx & 31;
    int h   = (idx >> 5) % heads;
    int row = idx / (32 * heads);
    int s   = row & (S_ - 1);
    float c  = cs[s * 32 + i];
    float si = sn[s * 32 + i];
    float* p = t + (size_t)row * heads * 64 + h * 64;
    float a  = p[i];
    float b2 = p[i + 32];
    p[i]      = a * c - b2 * si;
    p[i + 32] = b2 * c + a * si;
}

// ---------------------------------------------------------------------------
// Causal flash attention, fp32. One thread = one query row; 64x64 K/V tiles
// in smem read via broadcast float4 LDS. Online softmax in 16-key chunks.
// grid = (S/64, B*H), block = 64.
// ---------------------------------------------------------------------------
__global__ __launch_bounds__(64) void flash_kernel(const float* __restrict__ q,
                                                   const float* __restrict__ k,
                                                   const float* __restrict__ v,
                                                   float* __restrict__ o) {
    __shared__ float Ks[64][64];
    __shared__ float Vs[64][64];

    const int tid   = threadIdx.x;
    const int qtile = blockIdx.x;
    const int bh    = blockIdx.y;
    const int b     = bh >> 5;   // / H_
    const int h     = bh & 31;
    const int kvh   = h >> 2;    // h / (H_/KV_)
    const int qrow  = qtile * 64 + tid;

    const float* qp = q + (size_t)(b * S_ + qrow) * (H_ * HD_) + h * HD_;
    float qr[64];
#pragma unroll
    for (int d = 0; d < 64; d++) qr[d] = qp[d] * 0.125f;  // 1/sqrt(64)

    float acc[64];
#pragma unroll
    for (int d = 0; d < 64; d++) acc[d] = 0.f;
    float m = -1e30f, l = 0.f;

    const float* kbase = k + (size_t)(b * S_) * (KV_ * HD_) + kvh * HD_;
    const float* vbase = v + (size_t)(b * S_) * (KV_ * HD_) + kvh * HD_;

    for (int kt = 0; kt <= qtile; kt++) {
        const float* kp = kbase + (size_t)kt * 64 * (KV_ * HD_);
        const float* vp = vbase + (size_t)kt * 64 * (KV_ * HD_);
#pragma unroll 4
        for (int r = 0; r < 64; r++) {
            Ks[r][tid] = kp[(size_t)r * (KV_ * HD_) + tid];
            Vs[r][tid] = vp[(size_t)r * (KV_ * HD_) + tid];
        }
        __syncthreads();

        const bool last = (kt == qtile);
#pragma unroll
        for (int c = 0; c < 4; c++) {
            if (last && c * 16 > tid) break;  // whole chunk masked
            float p[16];
            float cm = -1e30f;
#pragma unroll
            for (int jj = 0; jj < 16; jj++) {
                int j = c * 16 + jj;
                const float4* kr = reinterpret_cast<const float4*>(&Ks[j][0]);
                float s = 0.f;
#pragma unroll
                for (int d4 = 0; d4 < 16; d4++) {
                    float4 kk4 = kr[d4];
                    s += qr[4 * d4 + 0] * kk4.x + qr[4 * d4 + 1] * kk4.y +
                         qr[4 * d4 + 2] * kk4.z + qr[4 * d4 + 3] * kk4.w;
                }
                bool valid = (!last) || (j <= tid);
                p[jj] = valid ? s : -1e30f;
                if (valid) cm = fmaxf(cm, s);
            }
            float mnew  = fmaxf(m, cm);
            float scale = __expf(m - mnew);
            float sum = 0.f;
#pragma unroll
            for (int jj = 0; jj < 16; jj++) {
                float e = (p[jj] > -1e29f) ? __expf(p[jj] - mnew) : 0.f;
                p[jj] = e;
                sum += e;
            }
            l = l * scale + sum;
#pragma unroll
            for (int d = 0; d < 64; d++) acc[d] *= scale;
#pragma unroll
            for (int jj = 0; jj < 16; jj++) {
                float pj = p[jj];
                const float4* vr = reinterpret_cast<const float4*>(&Vs[c * 16 + jj][0]);
#pragma unroll
                for (int d4 = 0; d4 < 16; d4++) {
                    float4 vv = vr[d4];
                    acc[4 * d4 + 0] += pj * vv.x;
                    acc[4 * d4 + 1] += pj * vv.y;
                    acc[4 * d4 + 2] += pj * vv.z;
                    acc[4 * d4 + 3] += pj * vv.w;
                }
            }
            m = mnew;
        }
        __syncthreads();
    }

    float inv = 1.f / l;
    float* op = o + (size_t)(b * S_ + qrow) * (H_ * HD_) + h * HD_;
#pragma unroll
    for (int d = 0; d < 64; d++) op[d] = acc[d] * inv;
}

// ---------------------------------------------------------------------------
// Launcher. Inputs (metadata order): x, cos, sin, mask, wq, wk, wv, wo.
// mask unused (analytic causal masking is exact: -1e9 underflows to 0 prob).
// ---------------------------------------------------------------------------
extern "C" void kernel_launch(void* const* d_in, const int* in_sizes, int n_in,
                              void* d_out, int out_size) {
    const float* x    = (const float*)d_in[0];
    const float* cosb = (const float*)d_in[1];
    const float* sinb = (const float*)d_in[2];
    const float* wq   = (const float*)d_in[4];
    const float* wk   = (const float*)d_in[5];
    const float* wv   = (const float*)d_in[6];
    const float* wo   = (const float*)d_in[7];
    float* out = (float*)d_out;

    float *qb, *kb, *vb, *ab;
    cudaGetSymbolAddress((void**)&qb, g_q);
    cudaGetSymbolAddress((void**)&kb, g_k);
    cudaGetSymbolAddress((void**)&vb, g_v);
    cudaGetSymbolAddress((void**)&ab, g_attn);

    const int M = B_ * S_;  // 4096

    // QKV projections: C = x @ W^T
    gemm_nt<<<dim3((H_ * HD_) / 128, M / 128), 256>>>(x, wq, qb, M, H_ * HD_, D_);
    gemm_nt<<<dim3((KV_ * HD_) / 128, M / 128), 256>>>(x, wk, kb, M, KV_ * HD_, D_);
    gemm_nt<<<dim3((KV_ * HD_) / 128, M / 128), 256>>>(x, wv, vb, M, KV_ * HD_, D_);

    // RoPE on q and k
    rope_kernel<<<(M * H_ * 32 + 255) / 256, 256>>>(qb, cosb, sinb, H_);
    rope_kernel<<<(M * KV_ * 32 + 255) / 256, 256>>>(kb, cosb, sinb, KV_);

    // Causal GQA flash attention
    flash_kernel<<<dim3(S_ / 64, B_ * H_), 64>>>(qb, kb, vb, ab);

    // Output projection: out = attn @ wo^T
    gemm_nt<<<dim3(D_ / 128, M / 128), 256>>>(ab, wo, out, M, D_, H_ * HD_);
}

// round 16
// speedup vs baseline: 1.3953x; 1.3953x over previous
#include <cuda_runtime.h>
#include <cuda_bf16.h>
#include <stdint.h>
#include <math.h>

// Problem constants
#define B_   2
#define S_   2048
#define D_   2048
#define H_   32
#define KV_  8
#define HD_  64
#define MROWS (B_ * S_)   // 4096

// ---------------------------------------------------------------------------
// Scratch (static device globals: allocation-free, graph-safe)
// ---------------------------------------------------------------------------
__device__ __align__(1024) float g_q[MROWS * H_ * HD_];
__device__ __align__(1024) float g_k[MROWS * KV_ * HD_];
__device__ __align__(1024) float g_v[MROWS * KV_ * HD_];
__device__ __align__(1024) float g_attn[MROWS * H_ * HD_];
__device__ __align__(1024) float g_xt[MROWS * D_];
__device__ __align__(1024) float g_wqt[H_ * HD_ * D_];
__device__ __align__(1024) float g_wkt[KV_ * HD_ * D_];
__device__ __align__(1024) float g_wvt[KV_ * HD_ * D_];
__device__ __align__(1024) float g_wot[D_ * H_ * HD_];

// ---------------------------------------------------------------------------
// Helpers (sm_80-level PTX only — NO tcgen05/TMEM: harness compiles at the
// non-"a" target sm_103 where arch-specific instructions are rejected)
// ---------------------------------------------------------------------------
__device__ __forceinline__ uint32_t smem_u32(const void* p) {
    uint32_t a;
    asm("{ .reg .u64 t; cvta.to.shared.u64 t, %1; cvt.u32.u64 %0, t; }" : "=r"(a) : "l"(p));
    return a;
}

__device__ __forceinline__ void cp16(uint32_t saddr, const void* gptr) {
    asm volatile("cp.async.cg.shared.global [%0], [%1], 16;" :: "r"(saddr), "l"(gptr));
}

// tf32 warp mma: D(16x8) += A(16x8,row) * B(8x8,col)
__device__ __forceinline__ void mma_tf32(float* d, const uint32_t* a, const uint32_t* b) {
    asm volatile(
        "mma.sync.aligned.m16n8k8.row.col.f32.tf32.tf32.f32 "
        "{%0,%1,%2,%3}, {%4,%5,%6,%7}, {%8,%9}, {%0,%1,%2,%3};"
        : "+f"(d[0]), "+f"(d[1]), "+f"(d[2]), "+f"(d[3])
        : "r"(a[0]), "r"(a[1]), "r"(a[2]), "r"(a[3]),
          "r"(b[0]), "r"(b[1]));
}

// ---------------------------------------------------------------------------
// tf32 round-to-nearest conversion (elementwise; cvt.rna supported sm_80+)
// ---------------------------------------------------------------------------
__global__ void tf32_round_kernel(const float* __restrict__ src, float* __restrict__ dst, int n) {
    int i = blockIdx.x * 256 + threadIdx.x;
    if (i >= n) return;
    uint32_t r;
    asm("cvt.rna.tf32.f32 %0, %1;" : "=r"(r) : "f"(src[i]));
    dst[i] = __uint_as_float(r);
}

// ---------------------------------------------------------------------------
// tf32 mma.sync GEMM: C[4096, N] = A[4096, 2048] * B[N, 2048]^T
// Block tile 128x128xBK32, 256 thr = 8 warps (2M x 4N), warp tile 64x32.
// Double-buffered cp.async. grid = (N/128, 32).
// ---------------------------------------------------------------------------
#define BM 128
#define BN 128
#define BK 32
#define KDIM 2048
#define NCHUNK (KDIM / BK)        // 64
#define ASTR 36                    // BK + 4 pad, floats
#define TILE_FLOATS (BM * ASTR)    // 4608 floats per buffer
#define GEMM_SMEM (4 * TILE_FLOATS * 4)  // A(2 buf) + B(2 buf) = 73728 B

__global__ __launch_bounds__(256, 1) void gemm_mma(const float* __restrict__ A,
                                                   const float* __restrict__ Bm,
                                                   float* __restrict__ C, int N) {
    extern __shared__ float smem[];
    float* As = smem;                     // [2][128][36]
    float* Bs = smem + 2 * TILE_FLOATS;   // [2][128][36]
    const uint32_t As_u = smem_u32(As);
    const uint32_t Bs_u = smem_u32(Bs);

    const int tid   = threadIdx.x;
    const int lane  = tid & 31;
    const int warp  = tid >> 5;
    const int warpM = warp >> 2;          // 0..1
    const int warpN = warp & 3;           // 0..3
    const int bx = blockIdx.x, by = blockIdx.y;

    const float* Ab = A  + (size_t)by * BM * KDIM;
    const float* Bb = Bm + (size_t)bx * BN * KDIM;

    // async loader: 1024 float4 per tile (A and B), 4 per thread each
    auto load_chunk = [&](int buf, int k0) {
        const uint32_t dA = As_u + buf * TILE_FLOATS * 4;
        const uint32_t dB = Bs_u + buf * TILE_FLOATS * 4;
#pragma unroll
        for (int j = 0; j < 4; j++) {
            int idx = tid + 256 * j;        // 0..1023
            int row = idx >> 3, c4 = idx & 7;
            uint32_t soff = (uint32_t)(row * ASTR + c4 * 4) * 4;
            cp16(dA + soff, Ab + (size_t)row * KDIM + k0 + c4 * 4);
            cp16(dB + soff, Bb + (size_t)row * KDIM + k0 + c4 * 4);
        }
    };

    float acc[4][4][4];
#pragma unroll
    for (int mt = 0; mt < 4; mt++)
#pragma unroll
        for (int nt = 0; nt < 4; nt++)
#pragma unroll
            for (int i = 0; i < 4; i++) acc[mt][nt][i] = 0.f;

    load_chunk(0, 0);
    asm volatile("cp.async.commit_group;" ::: "memory");

    const int lq = lane >> 2;   // 0..7
    const int lr = lane & 3;    // 0..3

    for (int c = 0; c < NCHUNK; ++c) {
        if (c + 1 < NCHUNK) {
            load_chunk((c + 1) & 1, (c + 1) * BK);
            asm volatile("cp.async.commit_group;" ::: "memory");
            asm volatile("cp.async.wait_group 1;" ::: "memory");
        } else {
            asm volatile("cp.async.wait_group 0;" ::: "memory");
        }
        __syncthreads();

        const float* Abuf = As + (c & 1) * TILE_FLOATS;
        const float* Bbuf = Bs + (c & 1) * TILE_FLOATS;

#pragma unroll
        for (int ks = 0; ks < 4; ks++) {
            const int k0 = ks * 8 + lr;
            uint32_t af[4][4], bf[4][2];
#pragma unroll
            for (int mt = 0; mt < 4; mt++) {
                int r0 = warpM * 64 + mt * 16 + lq;
                af[mt][0] = __float_as_uint(Abuf[r0 * ASTR + k0]);
                af[mt][1] = __float_as_uint(Abuf[(r0 + 8) * ASTR + k0]);
                af[mt][2] = __float_as_uint(Abuf[r0 * ASTR + k0 + 4]);
                af[mt][3] = __float_as_uint(Abuf[(r0 + 8) * ASTR + k0 + 4]);
            }
#pragma unroll
            for (int nt = 0; nt < 4; nt++) {
                int n0 = warpN * 32 + nt * 8 + lq;
                bf[nt][0] = __float_as_uint(Bbuf[n0 * ASTR + k0]);
                bf[nt][1] = __float_as_uint(Bbuf[n0 * ASTR + k0 + 4]);
            }
#pragma unroll
            for (int mt = 0; mt < 4; mt++)
#pragma unroll
                for (int nt = 0; nt < 4; nt++)
                    mma_tf32(acc[mt][nt], af[mt], bf[nt]);
        }
        __syncthreads();
    }

    // Epilogue: c0,c1 -> (row, 2*lr+{0,1}); c2,c3 -> (row+8, same cols)
#pragma unroll
    for (int mt = 0; mt < 4; mt++) {
#pragma unroll
        for (int nt = 0; nt < 4; nt++) {
            int m0 = by * BM + warpM * 64 + mt * 16 + lq;
            int n0 = bx * BN + warpN * 32 + nt * 8 + 2 * lr;
            float2 lo = make_float2(acc[mt][nt][0], acc[mt][nt][1]);
            float2 hi = make_float2(acc[mt][nt][2], acc[mt][nt][3]);
            *reinterpret_cast<float2*>(C + (size_t)m0 * N + n0)       = lo;
            *reinterpret_cast<float2*>(C + (size_t)(m0 + 8) * N + n0) = hi;
        }
    }
}

// ---------------------------------------------------------------------------
// RoPE (in place): t shape (B*S, heads*64). Pair (i, i+32) rotated.
// ---------------------------------------------------------------------------
__global__ void rope_kernel(float* __restrict__ t, const float* __restrict__ cs,
                            const float* __restrict__ sn, int heads) {
    int idx = blockIdx.x * blockDim.x + threadIdx.x;
    int total = B_ * S_ * heads * 32;
    if (idx >= total) return;
    int i   = idx & 31;
    int h   = (idx >> 5) % heads;
    int row = idx / (32 * heads);
    int s   = row & (S_ - 1);
    float c  = cs[s * 32 + i];
    float si = sn[s * 32 + i];
    float* p = t + (size_t)row * heads * 64 + h * 64;
    float a  = p[i];
    float b2 = p[i + 32];
    p[i]      = a * c - b2 * si;
    p[i + 32] = b2 * c + a * si;
}

// ---------------------------------------------------------------------------
// Causal flash attention, fp32; output tf32-rounded for the out-projection.
// grid = (S/64, B*H), block = 64.
// ---------------------------------------------------------------------------
__global__ __launch_bounds__(64) void flash_kernel(const float* __restrict__ q,
                                                   const float* __restrict__ k,
                                                   const float* __restrict__ v,
                                                   float* __restrict__ o) {
    __shared__ float Ks[64][64];
    __shared__ float Vs[64][64];

    const int tid   = threadIdx.x;
    const int qtile = blockIdx.x;
    const int bh    = blockIdx.y;
    const int b     = bh >> 5;
    const int h     = bh & 31;
    const int kvh   = h >> 2;
    const int qrow  = qtile * 64 + tid;

    const float* qp = q + (size_t)(b * S_ + qrow) * (H_ * HD_) + h * HD_;
    float qr[64];
#pragma unroll
    for (int d = 0; d < 64; d++) qr[d] = qp[d] * 0.125f;

    float acc[64];
#pragma unroll
    for (int d = 0; d < 64; d++) acc[d] = 0.f;
    float m = -1e30f, l = 0.f;

    const float* kbase = k + (size_t)(b * S_) * (KV_ * HD_) + kvh * HD_;
    const float* vbase = v + (size_t)(b * S_) * (KV_ * HD_) + kvh * HD_;

    for (int kt = 0; kt <= qtile; kt++) {
        const float* kp = kbase + (size_t)kt * 64 * (KV_ * HD_);
        const float* vp = vbase + (size_t)kt * 64 * (KV_ * HD_);
#pragma unroll 4
        for (int r = 0; r < 64; r++) {
            Ks[r][tid] = kp[(size_t)r * (KV_ * HD_) + tid];
            Vs[r][tid] = vp[(size_t)r * (KV_ * HD_) + tid];
        }
        __syncthreads();

        const bool last = (kt == qtile);
#pragma unroll
        for (int c = 0; c < 4; c++) {
            if (last && c * 16 > tid) break;
            float p[16];
            float cm = -1e30f;
#pragma unroll
            for (int jj = 0; jj < 16; jj++) {
                int j = c * 16 + jj;
                const float4* kr = reinterpret_cast<const float4*>(&Ks[j][0]);
                float s = 0.f;
#pragma unroll
                for (int d4 = 0; d4 < 16; d4++) {
                    float4 kk4 = kr[d4];
                    s += qr[4 * d4 + 0] * kk4.x + qr[4 * d4 + 1] * kk4.y +
                         qr[4 * d4 + 2] * kk4.z + qr[4 * d4 + 3] * kk4.w;
                }
                bool valid = (!last) || (j <= tid);
                p[jj] = valid ? s : -1e30f;
                if (valid) cm = fmaxf(cm, s);
            }
            float mnew  = fmaxf(m, cm);
            float scale = __expf(m - mnew);
            float sum = 0.f;
#pragma unroll
            for (int jj = 0; jj < 16; jj++) {
                float e = (p[jj] > -1e29f) ? __expf(p[jj] - mnew) : 0.f;
                p[jj] = e;
                sum += e;
            }
            l = l * scale + sum;
#pragma unroll
            for (int d = 0; d < 64; d++) acc[d] *= scale;
#pragma unroll
            for (int jj = 0; jj < 16; jj++) {
                float pj = p[jj];
                const float4* vr = reinterpret_cast<const float4*>(&Vs[c * 16 + jj][0]);
#pragma unroll
                for (int d4 = 0; d4 < 16; d4++) {
                    float4 vv = vr[d4];
                    acc[4 * d4 + 0] += pj * vv.x;
                    acc[4 * d4 + 1] += pj * vv.y;
                    acc[4 * d4 + 2] += pj * vv.z;
                    acc[4 * d4 + 3] += pj * vv.w;
                }
            }
            m = mnew;
        }
        __syncthreads();
    }

    float inv = 1.f / l;
    float* op = o + (size_t)(b * S_ + qrow) * (H_ * HD_) + h * HD_;
#pragma unroll
    for (int d = 0; d < 64; d++) {
        uint32_t r;
        float val = acc[d] * inv;
        asm("cvt.rna.tf32.f32 %0, %1;" : "=r"(r) : "f"(val));  // pre-round for tf32 GEMM
        op[d] = __uint_as_float(r);
    }
}

// ---------------------------------------------------------------------------
// Launcher. Inputs: x, cos, sin, mask, wq, wk, wv, wo. mask unused (analytic
// causal masking is exact: -1e9 scores underflow to 0 probability in fp32).
// ---------------------------------------------------------------------------
extern "C" void kernel_launch(void* const* d_in, const int* in_sizes, int n_in,
                              void* d_out, int out_size) {
    const float* x    = (const float*)d_in[0];
    const float* cosb = (const float*)d_in[1];
    const float* sinb = (const float*)d_in[2];
    const float* wq   = (const float*)d_in[4];
    const float* wk   = (const float*)d_in[5];
    const float* wv   = (const float*)d_in[6];
    const float* wo   = (const float*)d_in[7];
    float* out = (float*)d_out;

    float *qb, *kb, *vb, *ab, *xt, *wqt, *wkt, *wvt, *wot;
    cudaGetSymbolAddress((void**)&qb,  g_q);
    cudaGetSymbolAddress((void**)&kb,  g_k);
    cudaGetSymbolAddress((void**)&vb,  g_v);
    cudaGetSymbolAddress((void**)&ab,  g_attn);
    cudaGetSymbolAddress((void**)&xt,  g_xt);
    cudaGetSymbolAddress((void**)&wqt, g_wqt);
    cudaGetSymbolAddress((void**)&wkt, g_wkt);
    cudaGetSymbolAddress((void**)&wvt, g_wvt);
    cudaGetSymbolAddress((void**)&wot, g_wot);

    cudaFuncSetAttribute(gemm_mma, cudaFuncAttributeMaxDynamicSharedMemorySize, GEMM_SMEM);

    // tf32-round inputs (round-to-nearest avoids truncation bias)
    int nx = MROWS * D_, nwq = H_ * HD_ * D_, nwk = KV_ * HD_ * D_;
    tf32_round_kernel<<<(nx + 255) / 256, 256>>>(x, xt, nx);
    tf32_round_kernel<<<(nwq + 255) / 256, 256>>>(wq, wqt, nwq);
    tf32_round_kernel<<<(nwk + 255) / 256, 256>>>(wk, wkt, nwk);
    tf32_round_kernel<<<(nwk + 255) / 256, 256>>>(wv, wvt, nwk);
    tf32_round_kernel<<<(nwq + 255) / 256, 256>>>(wo, wot, nwq);

    // QKV projections on tensor cores (tf32 mma.sync)
    gemm_mma<<<dim3((H_ * HD_) / BN, MROWS / BM), 256, GEMM_SMEM>>>(xt, wqt, qb, H_ * HD_);
    gemm_mma<<<dim3((KV_ * HD_) / BN, MROWS / BM), 256, GEMM_SMEM>>>(xt, wkt, kb, KV_ * HD_);
    gemm_mma<<<dim3((KV_ * HD_) / BN, MROWS / BM), 256, GEMM_SMEM>>>(xt, wvt, vb, KV_ * HD_);

    // RoPE
    rope_kernel<<<(MROWS * H_ * 32 + 255) / 256, 256>>>(qb, cosb, sinb, H_);
    rope_kernel<<<(MROWS * KV_ * 32 + 255) / 256, 256>>>(kb, cosb, sinb, KV_);

    // Causal GQA flash attention (fp32)
    flash_kernel<<<dim3(S_ / 64, B_ * H_), 64>>>(qb, kb, vb, ab);

    // Output projection on tensor cores (tf32 mma.sync)
    gemm_mma<<<dim3(D_ / BN, MROWS / BM), 256, GEMM_SMEM>>>(ab, wot, out, D_);
}